// round 4
// baseline (speedup 1.0000x reference)
#include <cuda_runtime.h>
#include <math.h>
#include <stdint.h>

// Problem constants (fixed by the dataset)
#define NN      4096
#define MM      2048
#define DVV     3
#define DCC     6
#define EE      (NN*DVV)      // 12288
#define BB      2048
#define NITER   5
#define THREADS 1024
#define CN_T    (MM/THREADS)  // 2 CN tasks per thread (each covers 2 rows)
#define VN_T    (NN/THREADS)  // 4 VN tasks per thread

// SMEM: msg2 (E x f32x2) + llr2 (N x f32x2) = 98304 + 32768 = 131072 B
#define SMEM_BYTES (EE*8 + NN*8)

typedef unsigned long long ull;

// ---------------------------------------------------------------------------
// f32x2 + MUFU helpers
// ---------------------------------------------------------------------------
__device__ __forceinline__ float ex2a(float x){ float r; asm("ex2.approx.ftz.f32 %0, %1;" : "=f"(r) : "f"(x)); return r; }
__device__ __forceinline__ float lg2a(float x){ float r; asm("lg2.approx.ftz.f32 %0, %1;" : "=f"(r) : "f"(x)); return r; }

__device__ __forceinline__ ull  pk2(float a, float b){ ull r; asm("mov.b64 %0, {%1, %2};" : "=l"(r) : "f"(a), "f"(b)); return r; }
__device__ __forceinline__ void upk2(ull x, float& a, float& b){ asm("mov.b64 {%0, %1}, %2;" : "=f"(a), "=f"(b) : "l"(x)); }
__device__ __forceinline__ ull  fma2(ull a, ull b, ull c){ ull r; asm("fma.rn.f32x2 %0, %1, %2, %3;" : "=l"(r) : "l"(a), "l"(b), "l"(c)); return r; }
__device__ __forceinline__ ull  mul2(ull a, ull b){ ull r; asm("mul.rn.f32x2 %0, %1, %2;" : "=l"(r) : "l"(a), "l"(b)); return r; }
__device__ __forceinline__ ull  add2(ull a, ull b){ ull r; asm("add.rn.f32x2 %0, %1, %2;" : "=l"(r) : "l"(a), "l"(b)); return r; }

#define LOG2E_F 1.4426950408889634f
#define LN2_F   0.6931471805599453f
#define FMAX_F  27.631021115928547f   /* -ln(1e-12): emulates log(|t|+eps) floor */
#define MAGMAX  16.635532f            /* 2*atanh(float(1-1e-7)): emulates CLIP   */

// f(x) = -ln(tanh(x/2)) on a pair of nonneg inputs. Self-inverse.
// 4 MUFU + packed f32x2 chains for the rest.
__device__ __forceinline__ void f_op2(float al, float ah, float& rl, float& rh)
{
    // packed constants (loop-invariant; CSE'd/hoisted by the compiler)
    const ull C27 = pk2(0.2857143f,  0.2857143f);   // 2/7
    const ull C25 = pk2(0.4f,        0.4f);         // 2/5
    const ull C23 = pk2(0.66666667f, 0.66666667f);  // 2/3
    const ull C2  = pk2(2.0f,        2.0f);
    const ull K6  = pk2(3.4171076e-4f,  3.4171076e-4f);
    const ull K4  = pk2(-4.8611111e-3f, -4.8611111e-3f);
    const ull K2  = pk2(8.3333333e-2f,  8.3333333e-2f);
    const ull NL2 = pk2(-LN2_F, -LN2_F);
    const ull PL2 = pk2( LN2_F,  LN2_F);

    // regime A (a >= 1): f = 2*atanh(u), u = e^{-a}
    float ul = ex2a(-al * LOG2E_F);
    float uh = ex2a(-ah * LOG2E_F);
    ull u  = pk2(ul, uh);
    ull us = mul2(u, u);
    ull q  = fma2(us, C27, C25);
    q      = fma2(us, q,   C23);
    q      = fma2(us, q,   C2);
    ull fL = mul2(u, q);

    // regime B (a < 1): f = ln2*(1 - lg2(a)) + a^2/12 - 7a^4/1440 + 62a^6/181440
    float ll = lg2a(al);
    float lh = lg2a(ah);
    ull a2   = pk2(al, ah);
    ull y    = mul2(a2, a2);
    ull p    = fma2(y, K6, K4);
    p        = fma2(y, p,  K2);
    ull base = fma2(pk2(ll, lh), NL2, PL2);
    ull fS   = fma2(y, p, base);

    float fLl, fLh, fSl, fSh;
    upk2(fL, fLl, fLh);
    upk2(fS, fSl, fSh);
    rl = (al >= 1.0f) ? fLl : fSl;
    rh = (ah >= 1.0f) ? fLh : fSh;
}

// ---------------------------------------------------------------------------
// Persistent scratch (static globals: no runtime allocation)
// ---------------------------------------------------------------------------
__device__ int   g_cnt[MM];
__device__ int   g_tmp[EE];        // g_tmp[m*6+slot] = edge id (atomic order)
__device__ uint4 g_cnp[MM * 3];    // per CN: 6 x u32 byte-offsets (e*8), 6 x f32 weights

// ---------------------------------------------------------------------------
// Prep kernels (deterministic after the sort)
// ---------------------------------------------------------------------------
__global__ void prep_zero()
{
    int i = blockIdx.x * blockDim.x + threadIdx.x;
    if (i < MM) g_cnt[i] = 0;
}

__global__ void prep_fill(const int* __restrict__ cn_idx)
{
    int e = blockIdx.x * blockDim.x + threadIdx.x;
    if (e < EE) {
        int m = cn_idx[e];
        int p = atomicAdd(&g_cnt[m], 1);
        g_tmp[m * DCC + p] = e;
    }
}

__global__ void prep_pack(const float* __restrict__ w)
{
    int m = blockIdx.x * blockDim.x + threadIdx.x;
    if (m >= MM) return;
    int a[DCC];
#pragma unroll
    for (int j = 0; j < DCC; j++) a[j] = g_tmp[m * DCC + j];
    // sort ascending -> deterministic edge order matching jax scatter-add
#pragma unroll
    for (int i = 0; i < DCC - 1; i++)
#pragma unroll
        for (int j = 0; j < DCC - 1 - i; j++)
            if (a[j] > a[j + 1]) { int t = a[j]; a[j] = a[j + 1]; a[j + 1] = t; }

    uint4 p0, p1, p2;
    p0.x = (unsigned)(a[0] * 8); p0.y = (unsigned)(a[1] * 8);
    p0.z = (unsigned)(a[2] * 8); p0.w = (unsigned)(a[3] * 8);
    p1.x = (unsigned)(a[4] * 8); p1.y = (unsigned)(a[5] * 8);
    p1.z = __float_as_uint(w[a[0]]); p1.w = __float_as_uint(w[a[1]]);
    p2.x = __float_as_uint(w[a[2]]); p2.y = __float_as_uint(w[a[3]]);
    p2.z = __float_as_uint(w[a[4]]); p2.w = __float_as_uint(w[a[5]]);
    g_cnp[m * 3 + 0] = p0;
    g_cnp[m * 3 + 1] = p1;
    g_cnp[m * 3 + 2] = p2;
}

// ---------------------------------------------------------------------------
// Main BP kernel: one CTA per 2 batch rows, messages packed f32x2 in SMEM
// ---------------------------------------------------------------------------
__global__ __launch_bounds__(THREADS, 1)
void bp_kernel(const float* __restrict__ noise_r,
               float* __restrict__ out)
{
    extern __shared__ ull smem8[];
    ull* msg2 = smem8;          // EE entries: {rowA, rowB} per edge
    ull* llr2 = smem8 + EE;     // NN entries

    const int tid  = threadIdx.x;
    const int rowA = blockIdx.x * 2;
    const float* nra = noise_r + (size_t)rowA * NN;
    const float* nrb = nra + NN;

    const float NO_F = 0.3981071705534972f;   // 10^-0.4
    const float NSTD = 0.44615420f;           // sqrtf(no/2) in f32
    const ull   NEG1 = pk2(-1.0f, -1.0f);

    // llr + msg_vn init
    for (int v = tid; v < NN; v += THREADS) {
        float la = (4.0f * (1.0f + NSTD * nra[v])) / NO_F;
        float lb = (4.0f * (1.0f + NSTD * nrb[v])) / NO_F;
        ull l2 = pk2(la, lb);
        llr2[v] = l2;
        msg2[3 * v + 0] = l2;
        msg2[3 * v + 1] = l2;
        msg2[3 * v + 2] = l2;
    }
    __syncthreads();

    for (int it = 0; it < NITER; ++it) {
        // ---- check-node pass (tanh/log fused, both rows at once) ----
#pragma unroll
        for (int k = 0; k < CN_T; ++k) {
            const int m = tid + k * THREADS;
            const uint4 p0 = __ldg(&g_cnp[m * 3 + 0]);
            const uint4 p1 = __ldg(&g_cnp[m * 3 + 1]);
            const uint4 p2 = __ldg(&g_cnp[m * 3 + 2]);

            unsigned off[6] = { p0.x, p0.y, p0.z, p0.w, p1.x, p1.y };
            float    wgt[6] = { __uint_as_float(p1.z), __uint_as_float(p1.w),
                                __uint_as_float(p2.x), __uint_as_float(p2.y),
                                __uint_as_float(p2.z), __uint_as_float(p2.w) };

            ull      fv[6];
            unsigned sl = 0u, sh = 0u;   // per-row sign bitmasks (bit j)
            ull      S  = 0ull;          // packed {0.f, 0.f}
#pragma unroll
            for (int j = 0; j < 6; ++j) {
                ull mm = *reinterpret_cast<const ull*>(
                             reinterpret_cast<const char*>(smem8) + off[j]);
                float xl, xh; upk2(mm, xl, xh);
                xl *= wgt[j];
                xh *= wgt[j];
                sl |= (__float_as_uint(xl) >> 31) << j;
                sh |= (__float_as_uint(xh) >> 31) << j;
                float fl, fh;
                f_op2(fabsf(xl), fabsf(xh), fl, fh);
                fl = fminf(fl, FMAX_F);
                fh = fminf(fh, FMAX_F);
                fv[j] = pk2(fl, fh);
                S = add2(S, fv[j]);      // ascending edge order (matches ref)
            }
            const unsigned pl = __popc(sl) & 1u;
            const unsigned ph = __popc(sh) & 1u;
#pragma unroll
            for (int j = 0; j < 6; ++j) {
                ull e2 = fma2(fv[j], NEG1, S);      // S - fv[j]
                float el, eh; upk2(e2, el, eh);
                el = fmaxf(el, 0.0f);
                eh = fmaxf(eh, 0.0f);
                float gl, gh;
                f_op2(el, eh, gl, gh);              // = 2*atanh(clip(exp(-el)))
                gl = fminf(gl, MAGMAX);
                gh = fminf(gh, MAGMAX);
                unsigned rl = __float_as_uint(gl) | ((pl ^ ((sl >> j) & 1u)) << 31);
                unsigned rh = __float_as_uint(gh) | ((ph ^ ((sh >> j) & 1u)) << 31);
                *reinterpret_cast<ull*>(reinterpret_cast<char*>(smem8) + off[j]) =
                    pk2(__uint_as_float(rl), __uint_as_float(rh));
            }
        }
        __syncthreads();

        // ---- variable-node pass: the 3 edges of VN v are contiguous ----
        const bool last = (it == NITER - 1);
#pragma unroll
        for (int k = 0; k < VN_T; ++k) {
            const int v = tid + k * THREADS;
            ull m0 = msg2[3 * v + 0];
            ull m1 = msg2[3 * v + 1];
            ull m2 = msg2[3 * v + 2];
            ull s  = add2(add2(m0, m1), m2);   // ascending edge order
            ull lt = add2(llr2[v], s);
            if (last) {
                float a, b; upk2(lt, a, b);
                out[(size_t)rowA * NN + v]       = a;
                out[(size_t)(rowA + 1) * NN + v] = b;
            } else {
                msg2[3 * v + 0] = fma2(m0, NEG1, lt);
                msg2[3 * v + 1] = fma2(m1, NEG1, lt);
                msg2[3 * v + 2] = fma2(m2, NEG1, lt);
            }
        }
        __syncthreads();
    }
}

// ---------------------------------------------------------------------------
// Launch
// ---------------------------------------------------------------------------
extern "C" void kernel_launch(void* const* d_in, const int* in_sizes, int n_in,
                              void* d_out, int out_size)
{
    const float* noise_r = (const float*)d_in[0];
    // d_in[1] = noise_i (unused by the reference)
    const float* weights = (const float*)d_in[2];
    // d_in[3] = vn_idx (structural: e/3)
    const int*   cn_idx  = (const int*)d_in[4];
    float* out = (float*)d_out;

    (void)in_sizes; (void)n_in; (void)out_size;

    cudaFuncSetAttribute(bp_kernel, cudaFuncAttributeMaxDynamicSharedMemorySize, SMEM_BYTES);

    prep_zero<<<(MM + 255) / 256, 256>>>();
    prep_fill<<<(EE + 255) / 256, 256>>>(cn_idx);
    prep_pack<<<(MM + 255) / 256, 256>>>(weights);

    bp_kernel<<<BB / 2, THREADS, SMEM_BYTES>>>(noise_r, out);
}

// round 5
// speedup vs baseline: 1.0119x; 1.0119x over previous
#include <cuda_runtime.h>
#include <math.h>
#include <stdint.h>

// Problem constants (fixed by the dataset)
#define NN      4096
#define MM      2048
#define DVV     3
#define DCC     6
#define EE      (NN*DVV)      // 12288
#define BB      2048
#define NITER   5
#define THREADS 512
#define CN_GROUPS 2           // 4 CNs per thread, processed as 2 packed pairs
#define VN_K      2           // 2 x (4 consecutive VNs) per thread

// SMEM: msg (E f32) + llr (N f32) = 49152 + 16384 = 65536 B -> 2 CTAs/SM
#define SMEM_BYTES (EE*4 + NN*4)

typedef unsigned long long ull;

// ---------------------------------------------------------------------------
// f32x2 + MUFU helpers
// ---------------------------------------------------------------------------
__device__ __forceinline__ float ex2a(float x){ float r; asm("ex2.approx.ftz.f32 %0, %1;" : "=f"(r) : "f"(x)); return r; }
__device__ __forceinline__ float lg2a(float x){ float r; asm("lg2.approx.ftz.f32 %0, %1;" : "=f"(r) : "f"(x)); return r; }

__device__ __forceinline__ ull  pk2(float a, float b){ ull r; asm("mov.b64 %0, {%1, %2};" : "=l"(r) : "f"(a), "f"(b)); return r; }
__device__ __forceinline__ void upk2(ull x, float& a, float& b){ asm("mov.b64 {%0, %1}, %2;" : "=f"(a), "=f"(b) : "l"(x)); }
__device__ __forceinline__ ull  fma2(ull a, ull b, ull c){ ull r; asm("fma.rn.f32x2 %0, %1, %2, %3;" : "=l"(r) : "l"(a), "l"(b), "l"(c)); return r; }
__device__ __forceinline__ ull  mul2(ull a, ull b){ ull r; asm("mul.rn.f32x2 %0, %1, %2;" : "=l"(r) : "l"(a), "l"(b)); return r; }
__device__ __forceinline__ ull  add2(ull a, ull b){ ull r; asm("add.rn.f32x2 %0, %1, %2;" : "=l"(r) : "l"(a), "l"(b)); return r; }

#define LOG2E_F 1.4426950408889634f
#define LN2_F   0.6931471805599453f
#define FMAX_F  27.631021115928547f   /* -ln(1e-12): emulates log(|t|+eps) floor */
#define MAGMAX  16.635532f            /* 2*atanh(float(1-1e-7)): emulates CLIP   */

// f(x) = -ln(tanh(x/2)) on a pair of nonneg inputs (two different CNs, same row).
// Self-inverse. 4 MUFU + packed f32x2 chains.
__device__ __forceinline__ void f_op2(float al, float ah, float& rl, float& rh)
{
    const ull C27 = pk2(0.2857143f,  0.2857143f);   // 2/7
    const ull C25 = pk2(0.4f,        0.4f);         // 2/5
    const ull C23 = pk2(0.66666667f, 0.66666667f);  // 2/3
    const ull C2  = pk2(2.0f,        2.0f);
    const ull K6  = pk2(3.4171076e-4f,  3.4171076e-4f);
    const ull K4  = pk2(-4.8611111e-3f, -4.8611111e-3f);
    const ull K2  = pk2(8.3333333e-2f,  8.3333333e-2f);
    const ull NL2 = pk2(-LN2_F, -LN2_F);
    const ull PL2 = pk2( LN2_F,  LN2_F);

    // regime A (a >= 1): f = 2*atanh(u), u = e^{-a}
    float ul = ex2a(-al * LOG2E_F);
    float uh = ex2a(-ah * LOG2E_F);
    ull u  = pk2(ul, uh);
    ull us = mul2(u, u);
    ull q  = fma2(us, C27, C25);
    q      = fma2(us, q,   C23);
    q      = fma2(us, q,   C2);
    ull fL = mul2(u, q);

    // regime B (a < 1): f = ln2*(1 - lg2(a)) + a^2/12 - 7a^4/1440 + 62a^6/181440
    float ll = lg2a(al);
    float lh = lg2a(ah);
    ull a2   = pk2(al, ah);
    ull y    = mul2(a2, a2);
    ull p    = fma2(y, K6, K4);
    p        = fma2(y, p,  K2);
    ull base = fma2(pk2(ll, lh), NL2, PL2);
    ull fS   = fma2(y, p, base);

    float fLl, fLh, fSl, fSh;
    upk2(fL, fLl, fLh);
    upk2(fS, fSl, fSh);
    rl = (al >= 1.0f) ? fLl : fSl;
    rh = (ah >= 1.0f) ? fLh : fSh;
}

// ---------------------------------------------------------------------------
// Persistent scratch (static globals: no runtime allocation)
// ---------------------------------------------------------------------------
__device__ int   g_cnt[MM];
__device__ int   g_tmp[EE];        // g_tmp[m*6+slot] = edge id (atomic order)
__device__ uint4 g_cnp[MM * 3];    // per CN: [8 x u16 byte-offsets][6 x f32 weights]

// ---------------------------------------------------------------------------
// Prep kernels (deterministic after the sort)
// ---------------------------------------------------------------------------
__global__ void prep_zero()
{
    int i = blockIdx.x * blockDim.x + threadIdx.x;
    if (i < MM) g_cnt[i] = 0;
}

__global__ void prep_fill(const int* __restrict__ cn_idx)
{
    int e = blockIdx.x * blockDim.x + threadIdx.x;
    if (e < EE) {
        int m = cn_idx[e];
        int p = atomicAdd(&g_cnt[m], 1);
        g_tmp[m * DCC + p] = e;
    }
}

__global__ void prep_pack(const float* __restrict__ w)
{
    int m = blockIdx.x * blockDim.x + threadIdx.x;
    if (m >= MM) return;
    int a[DCC];
#pragma unroll
    for (int j = 0; j < DCC; j++) a[j] = g_tmp[m * DCC + j];
    // sort ascending -> deterministic edge order matching jax scatter-add
#pragma unroll
    for (int i = 0; i < DCC - 1; i++)
#pragma unroll
        for (int j = 0; j < DCC - 1 - i; j++)
            if (a[j] > a[j + 1]) { int t = a[j]; a[j] = a[j + 1]; a[j + 1] = t; }

    uint4 iw;   // 8 x u16 byte offsets (e*4 < 49152 fits u16), slots 6,7 = 0
    iw.x = (unsigned)(a[0] * 4) | ((unsigned)(a[1] * 4) << 16);
    iw.y = (unsigned)(a[2] * 4) | ((unsigned)(a[3] * 4) << 16);
    iw.z = (unsigned)(a[4] * 4) | ((unsigned)(a[5] * 4) << 16);
    iw.w = 0;
    g_cnp[m * 3 + 0] = iw;

    uint4 w0, w1;
    w0.x = __float_as_uint(w[a[0]]); w0.y = __float_as_uint(w[a[1]]);
    w0.z = __float_as_uint(w[a[2]]); w0.w = __float_as_uint(w[a[3]]);
    w1.x = __float_as_uint(w[a[4]]); w1.y = __float_as_uint(w[a[5]]);
    w1.z = 0u; w1.w = 0u;
    g_cnp[m * 3 + 1] = w0;
    g_cnp[m * 3 + 2] = w1;
}

// ---------------------------------------------------------------------------
// Main BP kernel: one CTA per batch row, 2 CTAs/SM, CN-pair packed math
// ---------------------------------------------------------------------------
__global__ __launch_bounds__(THREADS, 2)
void bp_kernel(const float* __restrict__ noise_r,
               float* __restrict__ out)
{
    extern __shared__ unsigned char smem_raw[];
    float*  msg  = reinterpret_cast<float*>(smem_raw);     // E floats
    float4* msg4 = reinterpret_cast<float4*>(smem_raw);    // E/4 float4
    float4* llr4 = reinterpret_cast<float4*>(msg + EE);    // N/4 float4

    const int row = blockIdx.x;
    const int tid = threadIdx.x;
    const float4* nr4 = reinterpret_cast<const float4*>(noise_r + (size_t)row * NN);

    const float NO_F = 0.3981071705534972f;   // 10^-0.4
    const float NSTD = 0.44615420f;           // sqrtf(no/2) in f32
    const ull   NEG1 = pk2(-1.0f, -1.0f);

    // ---- init: llr + msg_vn (vectorized) ----
#pragma unroll
    for (int k = 0; k < VN_K; ++k) {
        const int q = tid + k * THREADS;      // float4 index over VNs
        float4 n = nr4[q];
        float l0 = (4.0f * (1.0f + NSTD * n.x)) / NO_F;
        float l1 = (4.0f * (1.0f + NSTD * n.y)) / NO_F;
        float l2v = (4.0f * (1.0f + NSTD * n.z)) / NO_F;
        float l3 = (4.0f * (1.0f + NSTD * n.w)) / NO_F;
        llr4[q] = make_float4(l0, l1, l2v, l3);
        msg4[3 * q + 0] = make_float4(l0, l0, l0, l1);
        msg4[3 * q + 1] = make_float4(l1, l1, l2v, l2v);
        msg4[3 * q + 2] = make_float4(l2v, l3, l3, l3);
    }
    __syncthreads();

    for (int it = 0; it < NITER; ++it) {
        // ---- check-node pass: 4 CNs per thread as 2 packed pairs ----
#pragma unroll
        for (int g = 0; g < CN_GROUPS; ++g) {
            const int ma = tid + (2 * g) * THREADS;
            const int mb = ma + THREADS;
            const uint4 ia = __ldg(&g_cnp[ma * 3 + 0]);
            const uint4 wa0 = __ldg(&g_cnp[ma * 3 + 1]);
            const uint4 wa1 = __ldg(&g_cnp[ma * 3 + 2]);
            const uint4 ib = __ldg(&g_cnp[mb * 3 + 0]);
            const uint4 wb0 = __ldg(&g_cnp[mb * 3 + 1]);
            const uint4 wb1 = __ldg(&g_cnp[mb * 3 + 2]);

            unsigned offa[6] = { ia.x & 0xFFFFu, ia.x >> 16, ia.y & 0xFFFFu,
                                 ia.y >> 16,     ia.z & 0xFFFFu, ia.z >> 16 };
            unsigned offb[6] = { ib.x & 0xFFFFu, ib.x >> 16, ib.y & 0xFFFFu,
                                 ib.y >> 16,     ib.z & 0xFFFFu, ib.z >> 16 };
            float wgta[6] = { __uint_as_float(wa0.x), __uint_as_float(wa0.y),
                              __uint_as_float(wa0.z), __uint_as_float(wa0.w),
                              __uint_as_float(wa1.x), __uint_as_float(wa1.y) };
            float wgtb[6] = { __uint_as_float(wb0.x), __uint_as_float(wb0.y),
                              __uint_as_float(wb0.z), __uint_as_float(wb0.w),
                              __uint_as_float(wb1.x), __uint_as_float(wb1.y) };

            ull      fv[6];
            unsigned sa = 0u, sb = 0u;
            ull      S  = 0ull;          // packed {0.f, 0.f}
#pragma unroll
            for (int j = 0; j < 6; ++j) {
                float xa = *reinterpret_cast<const float*>(smem_raw + offa[j]) * wgta[j];
                float xb = *reinterpret_cast<const float*>(smem_raw + offb[j]) * wgtb[j];
                sa |= (__float_as_uint(xa) >> 31) << j;
                sb |= (__float_as_uint(xb) >> 31) << j;
                float fa, fb;
                f_op2(fabsf(xa), fabsf(xb), fa, fb);
                fa = fminf(fa, FMAX_F);
                fb = fminf(fb, FMAX_F);
                fv[j] = pk2(fa, fb);
                S = add2(S, fv[j]);      // ascending edge order (matches ref)
            }
            const unsigned pa = __popc(sa) & 1u;
            const unsigned pb = __popc(sb) & 1u;
#pragma unroll
            for (int j = 0; j < 6; ++j) {
                ull e2 = fma2(fv[j], NEG1, S);      // S - fv[j]
                float ea, eb; upk2(e2, ea, eb);
                ea = fmaxf(ea, 0.0f);
                eb = fmaxf(eb, 0.0f);
                float ga, gb;
                f_op2(ea, eb, ga, gb);              // = 2*atanh(clip(exp(-el)))
                ga = fminf(ga, MAGMAX);
                gb = fminf(gb, MAGMAX);
                unsigned ra = __float_as_uint(ga) | ((pa ^ ((sa >> j) & 1u)) << 31);
                unsigned rb = __float_as_uint(gb) | ((pb ^ ((sb >> j) & 1u)) << 31);
                *reinterpret_cast<float*>(smem_raw + offa[j]) = __uint_as_float(ra);
                *reinterpret_cast<float*>(smem_raw + offb[j]) = __uint_as_float(rb);
            }
        }
        __syncthreads();

        // ---- variable-node pass: 4 consecutive VNs per task (vectorized) ----
        const bool last = (it == NITER - 1);
#pragma unroll
        for (int k = 0; k < VN_K; ++k) {
            const int q = tid + k * THREADS;        // float4 index over VNs
            float4 A = msg4[3 * q + 0];             // v0: A.x A.y A.z | v1: A.w ..
            float4 Bv = msg4[3 * q + 1];            // v1: B.x B.y | v2: B.z B.w ..
            float4 C = msg4[3 * q + 2];             // v2: C.x | v3: C.y C.z C.w
            float4 L = llr4[q];
            float lt0 = L.x + ((A.x + A.y) + A.z);
            float lt1 = L.y + ((A.w + Bv.x) + Bv.y);
            float lt2 = L.z + ((Bv.z + Bv.w) + C.x);
            float lt3 = L.w + ((C.y + C.z) + C.w);
            if (last) {
                reinterpret_cast<float4*>(out + (size_t)row * NN)[q] =
                    make_float4(lt0, lt1, lt2, lt3);
            } else {
                msg4[3 * q + 0] = make_float4(lt0 - A.x, lt0 - A.y, lt0 - A.z, lt1 - A.w);
                msg4[3 * q + 1] = make_float4(lt1 - Bv.x, lt1 - Bv.y, lt2 - Bv.z, lt2 - Bv.w);
                msg4[3 * q + 2] = make_float4(lt2 - C.x, lt3 - C.y, lt3 - C.z, lt3 - C.w);
            }
        }
        __syncthreads();
    }
}

// ---------------------------------------------------------------------------
// Launch
// ---------------------------------------------------------------------------
extern "C" void kernel_launch(void* const* d_in, const int* in_sizes, int n_in,
                              void* d_out, int out_size)
{
    const float* noise_r = (const float*)d_in[0];
    // d_in[1] = noise_i (unused by the reference)
    const float* weights = (const float*)d_in[2];
    // d_in[3] = vn_idx (structural: e/3)
    const int*   cn_idx  = (const int*)d_in[4];
    float* out = (float*)d_out;

    (void)in_sizes; (void)n_in; (void)out_size;

    cudaFuncSetAttribute(bp_kernel, cudaFuncAttributeMaxDynamicSharedMemorySize, SMEM_BYTES);

    prep_zero<<<(MM + 255) / 256, 256>>>();
    prep_fill<<<(EE + 255) / 256, 256>>>(cn_idx);
    prep_pack<<<(MM + 255) / 256, 256>>>(weights);

    bp_kernel<<<BB, THREADS, SMEM_BYTES>>>(noise_r, out);
}

// round 6
// speedup vs baseline: 1.1175x; 1.1043x over previous
#include <cuda_runtime.h>
#include <math.h>
#include <stdint.h>

// Problem constants (fixed by the dataset)
#define NN      4096
#define MM      2048
#define DVV     3
#define DCC     6
#define EE      (NN*DVV)      // 12288
#define BB      2048
#define NITER   5
#define THREADS 512
#define CN_T    (MM/THREADS)  // 4 CN tasks per thread (each covers 2 rows)
#define VN_T    (NN/THREADS)  // 8 VN tasks per thread

// SMEM: msg2 only (E x f32x2) = 98304 B -> 2 CTAs/SM (196KB of 228KB)
#define SMEM_BYTES (EE*8)

typedef unsigned long long ull;

// ---------------------------------------------------------------------------
// f32x2 + MUFU helpers
// ---------------------------------------------------------------------------
__device__ __forceinline__ float ex2a(float x){ float r; asm("ex2.approx.ftz.f32 %0, %1;" : "=f"(r) : "f"(x)); return r; }
__device__ __forceinline__ float lg2a(float x){ float r; asm("lg2.approx.ftz.f32 %0, %1;" : "=f"(r) : "f"(x)); return r; }

__device__ __forceinline__ ull  pk2(float a, float b){ ull r; asm("mov.b64 %0, {%1, %2};" : "=l"(r) : "f"(a), "f"(b)); return r; }
__device__ __forceinline__ void upk2(ull x, float& a, float& b){ asm("mov.b64 {%0, %1}, %2;" : "=f"(a), "=f"(b) : "l"(x)); }
__device__ __forceinline__ ull  fma2(ull a, ull b, ull c){ ull r; asm("fma.rn.f32x2 %0, %1, %2, %3;" : "=l"(r) : "l"(a), "l"(b), "l"(c)); return r; }
__device__ __forceinline__ ull  mul2(ull a, ull b){ ull r; asm("mul.rn.f32x2 %0, %1, %2;" : "=l"(r) : "l"(a), "l"(b)); return r; }
__device__ __forceinline__ ull  add2(ull a, ull b){ ull r; asm("add.rn.f32x2 %0, %1, %2;" : "=l"(r) : "l"(a), "l"(b)); return r; }

#define LOG2E_F 1.4426950408889634f
#define LN2_F   0.6931471805599453f
#define FMAX_F  27.631021115928547f   /* -ln(1e-12): emulates log(|t|+eps) floor */
#define MAGMAX  16.635532f            /* 2*atanh(float(1-1e-7)): emulates CLIP   */

// f(x) = -ln(tanh(x/2)) on a pair of nonneg inputs. Self-inverse.
// 4 MUFU + packed f32x2 chains.
__device__ __forceinline__ void f_op2(float al, float ah, float& rl, float& rh)
{
    const ull C27 = pk2(0.2857143f,  0.2857143f);   // 2/7
    const ull C25 = pk2(0.4f,        0.4f);         // 2/5
    const ull C23 = pk2(0.66666667f, 0.66666667f);  // 2/3
    const ull C2  = pk2(2.0f,        2.0f);
    const ull K6  = pk2(3.4171076e-4f,  3.4171076e-4f);
    const ull K4  = pk2(-4.8611111e-3f, -4.8611111e-3f);
    const ull K2  = pk2(8.3333333e-2f,  8.3333333e-2f);
    const ull NL2 = pk2(-LN2_F, -LN2_F);
    const ull PL2 = pk2( LN2_F,  LN2_F);

    // regime A (a >= 1): f = 2*atanh(u), u = e^{-a}
    float ul = ex2a(-al * LOG2E_F);
    float uh = ex2a(-ah * LOG2E_F);
    ull u  = pk2(ul, uh);
    ull us = mul2(u, u);
    ull q  = fma2(us, C27, C25);
    q      = fma2(us, q,   C23);
    q      = fma2(us, q,   C2);
    ull fL = mul2(u, q);

    // regime B (a < 1): f = ln2*(1 - lg2(a)) + a^2/12 - 7a^4/1440 + 62a^6/181440
    float ll = lg2a(al);
    float lh = lg2a(ah);
    ull a2   = pk2(al, ah);
    ull y    = mul2(a2, a2);
    ull p    = fma2(y, K6, K4);
    p        = fma2(y, p,  K2);
    ull base = fma2(pk2(ll, lh), NL2, PL2);
    ull fS   = fma2(y, p, base);

    float fLl, fLh, fSl, fSh;
    upk2(fL, fLl, fLh);
    upk2(fS, fSl, fSh);
    rl = (al >= 1.0f) ? fLl : fSl;
    rh = (ah >= 1.0f) ? fLh : fSh;
}

// ---------------------------------------------------------------------------
// Persistent scratch (static globals: no runtime allocation)
// ---------------------------------------------------------------------------
__device__ int   g_cnt[MM];
__device__ int   g_tmp[EE];        // g_tmp[m*6+slot] = edge id (atomic order)
__device__ uint4 g_cnp[MM * 3];    // per CN: 6 x u32 byte-offsets (e*8), 6 x f32 weights

// ---------------------------------------------------------------------------
// Prep kernels (deterministic after the sort)
// ---------------------------------------------------------------------------
__global__ void prep_zero()
{
    int i = blockIdx.x * blockDim.x + threadIdx.x;
    if (i < MM) g_cnt[i] = 0;
}

__global__ void prep_fill(const int* __restrict__ cn_idx)
{
    int e = blockIdx.x * blockDim.x + threadIdx.x;
    if (e < EE) {
        int m = cn_idx[e];
        int p = atomicAdd(&g_cnt[m], 1);
        g_tmp[m * DCC + p] = e;
    }
}

__global__ void prep_pack(const float* __restrict__ w)
{
    int m = blockIdx.x * blockDim.x + threadIdx.x;
    if (m >= MM) return;
    int a[DCC];
#pragma unroll
    for (int j = 0; j < DCC; j++) a[j] = g_tmp[m * DCC + j];
    // sort ascending -> deterministic edge order matching jax scatter-add
#pragma unroll
    for (int i = 0; i < DCC - 1; i++)
#pragma unroll
        for (int j = 0; j < DCC - 1 - i; j++)
            if (a[j] > a[j + 1]) { int t = a[j]; a[j] = a[j + 1]; a[j + 1] = t; }

    uint4 p0, p1, p2;
    p0.x = (unsigned)(a[0] * 8); p0.y = (unsigned)(a[1] * 8);
    p0.z = (unsigned)(a[2] * 8); p0.w = (unsigned)(a[3] * 8);
    p1.x = (unsigned)(a[4] * 8); p1.y = (unsigned)(a[5] * 8);
    p1.z = __float_as_uint(w[a[0]]); p1.w = __float_as_uint(w[a[1]]);
    p2.x = __float_as_uint(w[a[2]]); p2.y = __float_as_uint(w[a[3]]);
    p2.z = __float_as_uint(w[a[4]]); p2.w = __float_as_uint(w[a[5]]);
    g_cnp[m * 3 + 0] = p0;
    g_cnp[m * 3 + 1] = p1;
    g_cnp[m * 3 + 2] = p2;
}

// ---------------------------------------------------------------------------
// Main BP kernel: one CTA per 2 batch rows, msgs packed f32x2 in SMEM,
// llr in registers, 2 CTAs/SM.
// ---------------------------------------------------------------------------
__global__ __launch_bounds__(THREADS, 2)
void bp_kernel(const float* __restrict__ noise_r,
               float* __restrict__ out)
{
    extern __shared__ ull msg2[];   // EE entries: {rowA, rowB} per edge

    const int tid  = threadIdx.x;
    const int rowA = blockIdx.x * 2;
    const float* nra = noise_r + (size_t)rowA * NN;
    const float* nrb = nra + NN;

    const float NO_F = 0.3981071705534972f;   // 10^-0.4
    const float NSTD = 0.44615420f;           // sqrtf(no/2) in f32
    const ull   NEG1 = pk2(-1.0f, -1.0f);

    // llr lives in registers: one packed pair per owned VN
    ull llr_r[VN_T];

    // ---- init: llr (regs) + msg_vn (smem) ----
#pragma unroll
    for (int k = 0; k < VN_T; ++k) {
        const int v = tid + k * THREADS;
        float la = (4.0f * (1.0f + NSTD * nra[v])) / NO_F;
        float lb = (4.0f * (1.0f + NSTD * nrb[v])) / NO_F;
        ull l2 = pk2(la, lb);
        llr_r[k] = l2;
        msg2[3 * v + 0] = l2;
        msg2[3 * v + 1] = l2;
        msg2[3 * v + 2] = l2;
    }
    __syncthreads();

    for (int it = 0; it < NITER; ++it) {
        // ---- check-node pass (tanh/log fused, both rows at once) ----
#pragma unroll
        for (int k = 0; k < CN_T; ++k) {
            const int m = tid + k * THREADS;
            const uint4 p0 = __ldg(&g_cnp[m * 3 + 0]);
            const uint4 p1 = __ldg(&g_cnp[m * 3 + 1]);
            const uint4 p2 = __ldg(&g_cnp[m * 3 + 2]);

            unsigned off[6] = { p0.x, p0.y, p0.z, p0.w, p1.x, p1.y };
            float    wgt[6] = { __uint_as_float(p1.z), __uint_as_float(p1.w),
                                __uint_as_float(p2.x), __uint_as_float(p2.y),
                                __uint_as_float(p2.z), __uint_as_float(p2.w) };

            ull      fv[6];
            unsigned sl = 0u, sh = 0u;   // per-row sign bitmasks (bit j)
            ull      S  = 0ull;          // packed {0.f, 0.f}
#pragma unroll
            for (int j = 0; j < 6; ++j) {
                ull mm = *reinterpret_cast<const ull*>(
                             reinterpret_cast<const char*>(msg2) + off[j]);
                float xl, xh; upk2(mm, xl, xh);
                xl *= wgt[j];
                xh *= wgt[j];
                sl |= (__float_as_uint(xl) >> 31) << j;
                sh |= (__float_as_uint(xh) >> 31) << j;
                float fl, fh;
                f_op2(fabsf(xl), fabsf(xh), fl, fh);
                fl = fminf(fl, FMAX_F);
                fh = fminf(fh, FMAX_F);
                fv[j] = pk2(fl, fh);
                S = add2(S, fv[j]);      // ascending edge order (matches ref)
            }
            const unsigned pl = __popc(sl) & 1u;
            const unsigned ph = __popc(sh) & 1u;
#pragma unroll
            for (int j = 0; j < 6; ++j) {
                ull e2 = fma2(fv[j], NEG1, S);      // S - fv[j]
                float el, eh; upk2(e2, el, eh);
                el = fmaxf(el, 0.0f);
                eh = fmaxf(eh, 0.0f);
                float gl, gh;
                f_op2(el, eh, gl, gh);              // = 2*atanh(clip(exp(-el)))
                gl = fminf(gl, MAGMAX);
                gh = fminf(gh, MAGMAX);
                unsigned rl = __float_as_uint(gl) | ((pl ^ ((sl >> j) & 1u)) << 31);
                unsigned rh = __float_as_uint(gh) | ((ph ^ ((sh >> j) & 1u)) << 31);
                *reinterpret_cast<ull*>(reinterpret_cast<char*>(msg2) + off[j]) =
                    pk2(__uint_as_float(rl), __uint_as_float(rh));
            }
        }
        __syncthreads();

        // ---- variable-node pass: the 3 edges of VN v are contiguous ----
        const bool last = (it == NITER - 1);
#pragma unroll
        for (int k = 0; k < VN_T; ++k) {
            const int v = tid + k * THREADS;
            ull m0 = msg2[3 * v + 0];
            ull m1 = msg2[3 * v + 1];
            ull m2 = msg2[3 * v + 2];
            ull s  = add2(add2(m0, m1), m2);   // ascending edge order
            ull lt = add2(llr_r[k], s);
            if (last) {
                float a, b; upk2(lt, a, b);
                out[(size_t)rowA * NN + v]       = a;
                out[(size_t)(rowA + 1) * NN + v] = b;
            } else {
                msg2[3 * v + 0] = fma2(m0, NEG1, lt);
                msg2[3 * v + 1] = fma2(m1, NEG1, lt);
                msg2[3 * v + 2] = fma2(m2, NEG1, lt);
            }
        }
        __syncthreads();
    }
}

// ---------------------------------------------------------------------------
// Launch
// ---------------------------------------------------------------------------
extern "C" void kernel_launch(void* const* d_in, const int* in_sizes, int n_in,
                              void* d_out, int out_size)
{
    const float* noise_r = (const float*)d_in[0];
    // d_in[1] = noise_i (unused by the reference)
    const float* weights = (const float*)d_in[2];
    // d_in[3] = vn_idx (structural: e/3)
    const int*   cn_idx  = (const int*)d_in[4];
    float* out = (float*)d_out;

    (void)in_sizes; (void)n_in; (void)out_size;

    cudaFuncSetAttribute(bp_kernel, cudaFuncAttributeMaxDynamicSharedMemorySize, SMEM_BYTES);

    prep_zero<<<(MM + 255) / 256, 256>>>();
    prep_fill<<<(EE + 255) / 256, 256>>>(cn_idx);
    prep_pack<<<(MM + 255) / 256, 256>>>(weights);

    bp_kernel<<<BB / 2, THREADS, SMEM_BYTES>>>(noise_r, out);
}